// round 1
// baseline (speedup 1.0000x reference)
#include <cuda_runtime.h>

#define BB    32
#define NIN   2048
#define NHID  512
#define NOUT  10
#define TLEN  350
#define KSRM  100
#define KREF  32
#define THETA 10.0f
#define TT    25            // timesteps per GEMM1 tile
#define NTILE (TLEN / TT)   // 14 (exact)
#define NW    (NIN / 32)    // 64 bitmask words per (b,t)
#define HW    (NHID / 32)   // 16 bitmask words per (b,t)

// ---------------- device scratch (no allocations allowed) ----------------
__device__ float    g_W1T[NIN * NHID];          // 4 MB, W1 transposed [n][m]
__device__ unsigned g_bits1[BB * TLEN * NW];    // packed input spikes [b][t][w]
__device__ float    g_z1[BB * TLEN * NHID];     // W1 @ x, layout [b][t][m]
__device__ unsigned g_s1b[BB * TLEN * HW];      // packed layer-1 spikes
__device__ float    g_q[BB * NOUT * TLEN];      // W2 @ s1, layout [b][o][t]

// ---------------- K1: transpose W1 [NHID][NIN] -> W1T [NIN][NHID] --------
__global__ void k_transpose(const float* __restrict__ W1) {
    __shared__ float tile[32][33];
    int bx = blockIdx.x * 32;          // n base
    int by = blockIdx.y * 32;          // m base
    int tx = threadIdx.x, ty = threadIdx.y;
    #pragma unroll
    for (int j = 0; j < 32; j += 8)
        tile[ty + j][tx] = W1[(by + ty + j) * NIN + bx + tx];
    __syncthreads();
    #pragma unroll
    for (int j = 0; j < 32; j += 8)
        g_W1T[(bx + ty + j) * NHID + (by + tx)] = tile[tx][ty + j];
}

// ---------------- K0: pack binary input spikes into bitmasks -------------
__global__ void k_pack(const float* __restrict__ x) {
    int b = blockIdx.y;
    int w = blockIdx.x;
    for (int t = threadIdx.x; t < TLEN; t += blockDim.x) {
        unsigned word = 0;
        #pragma unroll
        for (int j = 0; j < 32; j++) {
            float v = x[((size_t)b * NIN + w * 32 + j) * TLEN + t]; // coalesced in t
            word |= (v > 0.5f) ? (1u << j) : 0u;
        }
        g_bits1[(b * TLEN + t) * NW + w] = word;
    }
}

// ---------------- K2: sparse-binary GEMM  z1 = W1 @ x --------------------
// CTA = (t-tile of TT, batch b), 512 threads (thread = output neuron m).
// One W1T row load is shared across all TT timesteps via smem accumulators.
__global__ __launch_bounds__(512) void k_gemm1() {
    extern __shared__ char smem_raw[];
    float*    acc   = (float*)smem_raw;                   // [512][TT], stride 25 (odd -> conflict-free)
    unsigned* sbits = (unsigned*)(acc + NHID * TT);       // [TT][NW]
    unsigned* tmask = sbits + TT * NW;                    // [NIN] per-n mask over the TT window

    int b   = blockIdx.y;
    int t0  = blockIdx.x * TT;
    int tid = threadIdx.x;

    #pragma unroll
    for (int i = 0; i < TT; i++) acc[tid * TT + i] = 0.f;

    for (int i = tid; i < TT * NW; i += 512)
        sbits[i] = g_bits1[(b * TLEN + t0) * NW + i];
    __syncthreads();

    // transpose bitmask: tmask[n] = which of the TT timesteps n spikes in
    for (int n = tid; n < NIN; n += 512) {
        int w = n >> 5, bit = n & 31;
        unsigned msk = 0;
        #pragma unroll
        for (int tt = 0; tt < TT; tt++)
            msk |= ((sbits[tt * NW + w] >> bit) & 1u) << tt;
        tmask[n] = msk;
    }
    __syncthreads();

    for (int n = 0; n < NIN; n++) {
        unsigned msk = tmask[n];          // smem broadcast, uniform across CTA
        if (msk == 0) continue;           // ~28% of rows survive for TT=25
        float wv = g_W1T[n * NHID + tid]; // coalesced, L2-resident
        do {
            int t = __ffs(msk) - 1;
            msk &= msk - 1;
            acc[tid * TT + t] += wv;      // conflict-free (stride 25)
        } while (msk);
    }

    #pragma unroll
    for (int tt = 0; tt < TT; tt++)
        g_z1[(b * TLEN + t0 + tt) * NHID + tid] = acc[tid * TT + tt];
}

// ------------- recursion constants for exact truncated SRM kernel --------
// eps(j) = (j/tau)*e^(1-j/tau) = Ceps * j * r^j,  r = e^(-1/tau), tau=10
// A[t] = r*A[t-1] + x[t] - r^K x[t-K]          (truncated geometric)
// Y[t] = r*(Y[t-1]+A[t-1]) - K r^K x[t-K]      (truncated j*r^j)
// a[t] = Ceps * Y[t]

// ---------------- K3: layer-1 SRM filter + spike (sequential in t) -------
__global__ void k_layer1() {
    __shared__ float srefk[KREF];
    int b = blockIdx.y;
    int m = blockIdx.x * 128 + threadIdx.x;
    if (threadIdx.x < KREF)
        srefk[threadIdx.x] = -2.0f * THETA * (float)threadIdx.x *
                             expf(1.0f - (float)threadIdx.x);
    __syncthreads();

    const float r    = expf(-0.1f);
    const float rK   = expf(-10.0f);
    const float KrK  = 100.0f * rK;
    const float Ceps = expf(1.0f) * 0.1f;

    float A = 0.f, Y = 0.f;
    unsigned hist = 0;   // bit i => spike at t-1-i  (refractory window d=1..31)
    for (int t = 0; t < TLEN; t++) {
        float xz = g_z1[(b * TLEN + t) * NHID + m];
        float xo = (t >= KSRM) ? g_z1[(b * TLEN + t - KSRM) * NHID + m] : 0.f;
        float Yn = r * (Y + A) - KrK * xo;
        A = r * A + xz - rK * xo;
        Y = Yn;
        float u = Ceps * Y;

        float refr = 0.f;
        unsigned hb = hist;
        while (hb) { int i = __ffs(hb) - 1; hb &= hb - 1; refr += srefk[i + 1]; }

        bool s = (u + refr >= THETA);
        hist = ((hist << 1) | (s ? 1u : 0u)) & 0x7FFFFFFFu;

        unsigned bal = __ballot_sync(0xFFFFFFFFu, s);
        if ((threadIdx.x & 31) == 0)
            g_s1b[(b * TLEN + t) * HW + (m >> 5)] = bal;
    }
}

// ---------------- K4: sparse-binary GEMM  q = W2 @ s1 --------------------
__global__ void k_gemm2(const float* __restrict__ W2) {
    __shared__ float w2t[NHID * NOUT];   // W2 transposed [m][o], 20 KB
    int b = blockIdx.x;
    for (int i = threadIdx.x; i < NHID * NOUT; i += blockDim.x) {
        int o = i / NHID, m = i % NHID;
        w2t[m * NOUT + o] = W2[i];
    }
    __syncthreads();

    for (int t = threadIdx.x; t < TLEN; t += blockDim.x) {
        float accv[NOUT];
        #pragma unroll
        for (int o = 0; o < NOUT; o++) accv[o] = 0.f;
        #pragma unroll
        for (int w = 0; w < HW; w++) {
            unsigned bits = g_s1b[(b * TLEN + t) * HW + w];
            while (bits) {
                int m = w * 32 + __ffs(bits) - 1;
                bits &= bits - 1;
                #pragma unroll
                for (int o = 0; o < NOUT; o++) accv[o] += w2t[m * NOUT + o];
            }
        }
        #pragma unroll
        for (int o = 0; o < NOUT; o++)
            g_q[(b * NOUT + o) * TLEN + t] = accv[o];
    }
}

// ---------------- K5: layer-2 SRM filter + spike -> output ---------------
__global__ void k_layer2(float* __restrict__ out) {
    __shared__ float srefk[KREF];
    int tid = threadIdx.x;                 // 0..319 == (b*NOUT + o)
    if (tid < KREF)
        srefk[tid] = -2.0f * THETA * (float)tid * expf(1.0f - (float)tid);
    __syncthreads();

    const float r    = expf(-0.1f);
    const float rK   = expf(-10.0f);
    const float KrK  = 100.0f * rK;
    const float Ceps = expf(1.0f) * 0.1f;

    const float* q  = g_q + tid * TLEN;
    float*       so = out + tid * TLEN;

    float A = 0.f, Y = 0.f;
    unsigned hist = 0;
    for (int t = 0; t < TLEN; t++) {
        float xz = q[t];
        float xo = (t >= KSRM) ? q[t - KSRM] : 0.f;
        float Yn = r * (Y + A) - KrK * xo;
        A = r * A + xz - rK * xo;
        Y = Yn;
        float u = Ceps * Y;

        float refr = 0.f;
        unsigned hb = hist;
        while (hb) { int i = __ffs(hb) - 1; hb &= hb - 1; refr += srefk[i + 1]; }

        bool s = (u + refr >= THETA);
        hist = ((hist << 1) | (s ? 1u : 0u)) & 0x7FFFFFFFu;
        so[t] = s ? 1.0f : 0.0f;           // divided by TS=1.0
    }
}

// ---------------- launch ----------------
extern "C" void kernel_launch(void* const* d_in, const int* in_sizes, int n_in,
                              void* d_out, int out_size) {
    const float* x  = (const float*)d_in[0];   // [32, 2048, 350]
    const float* W1 = (const float*)d_in[1];   // [512, 2048]
    const float* W2 = (const float*)d_in[2];   // [10, 512]
    float* out = (float*)d_out;                // [32, 10, 350]

    const int SMEM_K2 = NHID * TT * 4 + TT * NW * 4 + NIN * 4;  // 65792 B
    cudaFuncSetAttribute(k_gemm1, cudaFuncAttributeMaxDynamicSharedMemorySize,
                         SMEM_K2);

    k_transpose<<<dim3(NIN / 32, NHID / 32), dim3(32, 8)>>>(W1);
    k_pack<<<dim3(NW, BB), 128>>>(x);
    k_gemm1<<<dim3(NTILE, BB), 512, SMEM_K2>>>();
    k_layer1<<<dim3(NHID / 128, BB), 128>>>();
    k_gemm2<<<BB, 128>>>(W2);
    k_layer2<<<1, BB * NOUT>>>(out);
}

// round 2
// speedup vs baseline: 1.0128x; 1.0128x over previous
#include <cuda_runtime.h>

#define BB    32
#define NIN   2048
#define NHID  512
#define NOUT  10
#define TLEN  350
#define KSRM  100
#define KREF  32
#define THETA 10.0f
#define TT    25            // timesteps per GEMM1 tile
#define NTILE (TLEN / TT)   // 14
#define NW    (NIN / 32)    // 64
#define HW    (NHID / 32)   // 16
#define CC    14            // prefetch chunk for spike kernels (350 = 25*14)

// ---------------- device scratch ----------------
__device__ float    g_W1T[NIN * NHID];          // 4 MB, W1 transposed [n][m]
__device__ unsigned g_bits1[BB * TLEN * NW];    // packed input spikes [b][t][w]
__device__ float    g_z1[BB * TLEN * NHID];     // W1 @ x, layout [b][t][m]
__device__ unsigned g_s1b[BB * TLEN * HW];      // packed layer-1 spikes
__device__ float    g_q[BB * NOUT * TLEN];      // W2 @ s1, layout [b][o][t]

// ---------------- K1: transpose W1 ----------------
__global__ void k_transpose(const float* __restrict__ W1) {
    __shared__ float tile[32][33];
    int bx = blockIdx.x * 32, by = blockIdx.y * 32;
    int tx = threadIdx.x, ty = threadIdx.y;
    #pragma unroll
    for (int j = 0; j < 32; j += 8)
        tile[ty + j][tx] = W1[(by + ty + j) * NIN + bx + tx];
    __syncthreads();
    #pragma unroll
    for (int j = 0; j < 32; j += 8)
        g_W1T[(bx + ty + j) * NHID + (by + tx)] = tile[tx][ty + j];
}

// ---------------- K0: pack input spikes (float2-vectorized over t) -------
__global__ void k_pack(const float* __restrict__ x) {
    int b = blockIdx.y;
    int w = blockIdx.x;
    const float* xb = x + ((size_t)b * NIN + w * 32) * TLEN;
    for (int k = threadIdx.x; k < TLEN / 2; k += blockDim.x) {
        int t = k * 2;
        unsigned w0 = 0, w1 = 0;
        #pragma unroll
        for (int j = 0; j < 32; j++) {
            float2 v = *(const float2*)(xb + j * TLEN + t);
            w0 |= (v.x > 0.5f) ? (1u << j) : 0u;
            w1 |= (v.y > 0.5f) ? (1u << j) : 0u;
        }
        g_bits1[(b * TLEN + t    ) * NW + w] = w0;
        g_bits1[(b * TLEN + t + 1) * NW + w] = w1;
    }
}

// ---------------- K2: sparse-binary GEMM  z1 = W1 @ x --------------------
__global__ __launch_bounds__(512) void k_gemm1() {
    extern __shared__ char smem_raw[];
    float*    acc     = (float*)smem_raw;               // [512][TT] stride 25
    unsigned* sbits   = (unsigned*)(acc + NHID * TT);   // [TT][NW]
    unsigned* tmask   = sbits + TT * NW;                // [NIN]
    unsigned* activeb = tmask + NIN;                    // [NW] active-n bitmap

    int b   = blockIdx.y;
    int t0  = blockIdx.x * TT;
    int tid = threadIdx.x;

    #pragma unroll
    for (int i = 0; i < TT; i++) acc[tid * TT + i] = 0.f;

    for (int i = tid; i < TT * NW; i += 512)
        sbits[i] = g_bits1[(b * TLEN + t0) * NW + i];
    __syncthreads();

    // tmask[n]: which of the TT timesteps n spikes in
    for (int n = tid; n < NIN; n += 512) {
        int w = n >> 5, bit = n & 31;
        unsigned msk = 0;
        #pragma unroll
        for (int tt = 0; tt < TT; tt++)
            msk |= ((sbits[tt * NW + w] >> bit) & 1u) << tt;
        tmask[n] = msk;
    }
    __syncthreads();

    // active bitmap: bit j of activeb[w] <=> tmask[w*32+j] != 0
    for (int w = tid; w < NW; w += 512) {
        unsigned aw = 0;
        #pragma unroll
        for (int j = 0; j < 32; j++)
            aw |= (tmask[w * 32 + j] != 0u) ? (1u << j) : 0u;
        activeb[w] = aw;
    }
    __syncthreads();

    // deterministic ascending-n event loop over active rows only
    for (int w = 0; w < NW; w++) {
        unsigned aw = activeb[w];          // uniform smem broadcast
        while (aw) {
            int j = __ffs(aw) - 1; aw &= aw - 1;
            int n = w * 32 + j;
            unsigned msk = tmask[n];
            float wv = g_W1T[n * NHID + tid];  // coalesced, L2-resident
            do {
                int t = __ffs(msk) - 1; msk &= msk - 1;
                acc[tid * TT + t] += wv;       // conflict-free (stride 25)
            } while (msk);
        }
    }

    #pragma unroll
    for (int tt = 0; tt < TT; tt++)
        g_z1[(b * TLEN + t0 + tt) * NHID + tid] = acc[tid * TT + tt];
}

// ---------------- K3: layer-1 SRM filter + spike (chunked MLP) -----------
__global__ void k_layer1() {
    __shared__ float srefk[KREF];
    int b = blockIdx.y;
    int m = blockIdx.x * 128 + threadIdx.x;
    if (threadIdx.x < KREF)
        srefk[threadIdx.x] = -2.0f * THETA * (float)threadIdx.x *
                             expf(1.0f - (float)threadIdx.x);
    __syncthreads();

    const float r    = expf(-0.1f);
    const float rK   = expf(-10.0f);
    const float KrK  = 100.0f * rK;
    const float Ceps = expf(1.0f) * 0.1f;

    const float* zp = g_z1 + (size_t)b * TLEN * NHID + m;

    float A = 0.f, Y = 0.f;
    unsigned hist = 0;
    for (int t0 = 0; t0 < TLEN; t0 += CC) {
        float xz[CC], xo[CC];
        #pragma unroll
        for (int i = 0; i < CC; i++)                 // CC independent loads
            xz[i] = zp[(t0 + i) * NHID];
        #pragma unroll
        for (int i = 0; i < CC; i++)
            xo[i] = (t0 + i >= KSRM) ? zp[(t0 + i - KSRM) * NHID] : 0.f;
        #pragma unroll
        for (int i = 0; i < CC; i++) {
            float Yn = r * (Y + A) - KrK * xo[i];
            A = r * A + xz[i] - rK * xo[i];
            Y = Yn;
            float u = Ceps * Y;

            float refr = 0.f;
            unsigned hb = hist;
            while (hb) { int k = __ffs(hb) - 1; hb &= hb - 1; refr += srefk[k + 1]; }

            bool s = (u + refr >= THETA);
            hist = ((hist << 1) | (s ? 1u : 0u)) & 0x7FFFFFFFu;

            unsigned bal = __ballot_sync(0xFFFFFFFFu, s);
            if ((threadIdx.x & 31) == 0)
                g_s1b[(b * TLEN + t0 + i) * HW + (m >> 5)] = bal;
        }
    }
}

// ---------------- K4: sparse-binary GEMM  q = W2 @ s1 --------------------
__global__ void k_gemm2(const float* __restrict__ W2) {
    __shared__ float w2t[NHID * NOUT];   // W2 transposed [m][o], 20 KB
    int b = blockIdx.x;
    for (int i = threadIdx.x; i < NHID * NOUT; i += blockDim.x) {
        int o = i / NHID, m = i % NHID;
        w2t[m * NOUT + o] = W2[i];
    }
    __syncthreads();

    for (int t = threadIdx.x; t < TLEN; t += blockDim.x) {
        float accv[NOUT];
        #pragma unroll
        for (int o = 0; o < NOUT; o++) accv[o] = 0.f;
        #pragma unroll
        for (int w = 0; w < HW; w++) {
            unsigned bits = g_s1b[(b * TLEN + t) * HW + w];
            while (bits) {
                int m = w * 32 + __ffs(bits) - 1;
                bits &= bits - 1;
                #pragma unroll
                for (int o = 0; o < NOUT; o++) accv[o] += w2t[m * NOUT + o];
            }
        }
        #pragma unroll
        for (int o = 0; o < NOUT; o++)
            g_q[(b * NOUT + o) * TLEN + t] = accv[o];
    }
}

// ---------------- K5: layer-2 SRM filter + spike (chunked MLP) -----------
__global__ void k_layer2(float* __restrict__ out) {
    __shared__ float srefk[KREF];
    int tid = threadIdx.x;                 // 0..319 == b*NOUT + o
    if (tid < KREF)
        srefk[tid] = -2.0f * THETA * (float)tid * expf(1.0f - (float)tid);
    __syncthreads();

    const float r    = expf(-0.1f);
    const float rK   = expf(-10.0f);
    const float KrK  = 100.0f * rK;
    const float Ceps = expf(1.0f) * 0.1f;

    const float* q  = g_q + tid * TLEN;
    float*       so = out + tid * TLEN;

    float A = 0.f, Y = 0.f;
    unsigned hist = 0;
    for (int t0 = 0; t0 < TLEN; t0 += CC) {
        float xz[CC], xo[CC];
        #pragma unroll
        for (int i = 0; i < CC; i++)
            xz[i] = q[t0 + i];
        #pragma unroll
        for (int i = 0; i < CC; i++)
            xo[i] = (t0 + i >= KSRM) ? q[t0 + i - KSRM] : 0.f;
        #pragma unroll
        for (int i = 0; i < CC; i++) {
            float Yn = r * (Y + A) - KrK * xo[i];
            A = r * A + xz[i] - rK * xo[i];
            Y = Yn;
            float u = Ceps * Y;

            float refr = 0.f;
            unsigned hb = hist;
            while (hb) { int k = __ffs(hb) - 1; hb &= hb - 1; refr += srefk[k + 1]; }

            bool s = (u + refr >= THETA);
            hist = ((hist << 1) | (s ? 1u : 0u)) & 0x7FFFFFFFu;
            so[t0 + i] = s ? 1.0f : 0.0f;
        }
    }
}

// ---------------- launch ----------------
extern "C" void kernel_launch(void* const* d_in, const int* in_sizes, int n_in,
                              void* d_out, int out_size) {
    const float* x  = (const float*)d_in[0];   // [32, 2048, 350]
    const float* W1 = (const float*)d_in[1];   // [512, 2048]
    const float* W2 = (const float*)d_in[2];   // [10, 512]
    float* out = (float*)d_out;                // [32, 10, 350]

    const int SMEM_K2 = NHID * TT * 4 + TT * NW * 4 + NIN * 4 + NW * 4;
    cudaFuncSetAttribute(k_gemm1, cudaFuncAttributeMaxDynamicSharedMemorySize,
                         SMEM_K2);

    k_transpose<<<dim3(NIN / 32, NHID / 32), dim3(32, 8)>>>(W1);
    k_pack<<<dim3(NW, BB), 128>>>(x);
    k_gemm1<<<dim3(NTILE, BB), 512, SMEM_K2>>>();
    k_layer1<<<dim3(NHID / 128, BB), 128>>>();
    k_gemm2<<<BB, 128>>>(W2);
    k_layer2<<<1, BB * NOUT>>>(out);
}